// round 16
// baseline (speedup 1.0000x reference)
#include <cuda_runtime.h>
#include <cuda_bf16.h>
#include <math.h>
#include <stdint.h>

// ---------------- problem constants ----------------
#define NCLS 20
#define PP 2048
#define QQ 2048
#define CC 256
#define EPSV (0.0001f / 256.0f)
#define NP (NCLS * PP)

// ext row: [hi(256) | lo(256)] bf16 = 1024 bytes
#define ROW_BYTES 1024

// ---------------- device scratch (static; no runtime alloc) ----------------
__device__ float g_pos_sq[NCLS * PP];
__device__ float g_neg_sq[NCLS * QQ];
__device__ __align__(16) unsigned char g_posb[(size_t)NCLS * PP * ROW_BYTES];
__device__ __align__(16) unsigned char g_negb[(size_t)NCLS * QQ * ROW_BYTES];
__device__ float g_qpv[4 * NP];
__device__ int   g_qpj[4 * NP];
__device__ float g_qnv[4 * NP];
__device__ int   g_qnj[4 * NP];
__device__ int   g_hp[NP];
__device__ int   g_hn[NP];
__device__ float g_partial[NP / 8];

// ---------------- helpers ----------------
__device__ __forceinline__ uint32_t smem_u32(const void* p) {
    uint32_t a;
    asm("{ .reg .u64 t; cvta.to.shared.u64 t, %1; cvt.u32.u64 %0, t; }" : "=r"(a) : "l"(p));
    return a;
}
#define CP_ASYNC16(saddr, gptr) \
    asm volatile("cp.async.cg.shared.global [%0], [%1], 16;" :: "r"(saddr), "l"(gptr))
#define CP_COMMIT() asm volatile("cp.async.commit_group;" ::: "memory")
#define CP_WAIT1()  asm volatile("cp.async.wait_group 1;" ::: "memory")

#define LDSM_X4(r0, r1, r2, r3, a) \
    asm volatile("ldmatrix.sync.aligned.m8n8.x4.shared.b16 {%0,%1,%2,%3}, [%4];" \
                 : "=r"(r0), "=r"(r1), "=r"(r2), "=r"(r3) : "r"(a))
#define MMA16816(c0, c1, c2, c3, a0, a1, a2, a3, b0, b1) \
    asm volatile("mma.sync.aligned.m16n8k16.row.col.f32.bf16.bf16.f32 " \
                 "{%0,%1,%2,%3}, {%4,%5,%6,%7}, {%8,%9}, {%0,%1,%2,%3};" \
                 : "+f"(c0), "+f"(c1), "+f"(c2), "+f"(c3) \
                 : "r"(a0), "r"(a1), "r"(a2), "r"(a3), "r"(b0), "r"(b1))

__device__ __forceinline__ uint32_t pack_bf16(float a, float b) {
    __nv_bfloat16 ba = __float2bfloat16(a);
    __nv_bfloat16 bb = __float2bfloat16(b);
    uint16_t ua = *reinterpret_cast<uint16_t*>(&ba);
    uint16_t ub = *reinterpret_cast<uint16_t*>(&bb);
    return ((uint32_t)ub << 16) | (uint32_t)ua;
}
__device__ __forceinline__ float2 bf2f(uint32_t u) {
    __nv_bfloat162 b = *reinterpret_cast<__nv_bfloat162*>(&u);
    float2 r;
    r.x = __bfloat162float(b.x);
    r.y = __bfloat162float(b.y);
    return r;
}

// ---------------------------------------------------------------------------
// Kernel 1: gather + sigmoid -> hi|lo bf16 ext row + squared norm.
// (fp32 rows no longer stored; loss reconstructs x = hi + lo.)
// ---------------------------------------------------------------------------
__global__ void __launch_bounds__(64) gather_kernel(const float* __restrict__ feat,
                                                    const int* __restrict__ pidx,
                                                    const int* __restrict__ nidx) {
    int row = blockIdx.x;
    int t = threadIdx.x;
    int src;
    float* sqdst;
    unsigned char* rb;
    if (row < NP) {
        src = pidx[row];
        sqdst = g_pos_sq + row;
        rb = g_posb + (size_t)row * ROW_BYTES;
    } else {
        int r = row - NP;
        src = nidx[r];
        sqdst = g_neg_sq + r;
        rb = g_negb + (size_t)r * ROW_BYTES;
    }
    float4 v = *(const float4*)(feat + (size_t)src * CC + t * 4);
    float4 s;
    s.x = 1.0f / (1.0f + expf(-v.x));
    s.y = 1.0f / (1.0f + expf(-v.y));
    s.z = 1.0f / (1.0f + expf(-v.z));
    s.w = 1.0f / (1.0f + expf(-v.w));

    __nv_bfloat16 h0 = __float2bfloat16(s.x);
    __nv_bfloat16 h1 = __float2bfloat16(s.y);
    __nv_bfloat16 h2 = __float2bfloat16(s.z);
    __nv_bfloat16 h3 = __float2bfloat16(s.w);
    uint16_t u0 = *reinterpret_cast<uint16_t*>(&h0);
    uint16_t u1 = *reinterpret_cast<uint16_t*>(&h1);
    uint16_t u2 = *reinterpret_cast<uint16_t*>(&h2);
    uint16_t u3 = *reinterpret_cast<uint16_t*>(&h3);
    uint2 hv, lv;
    hv.x = ((uint32_t)u1 << 16) | u0;
    hv.y = ((uint32_t)u3 << 16) | u2;
    lv.x = pack_bf16(s.x - __bfloat162float(h0), s.y - __bfloat162float(h1));
    lv.y = pack_bf16(s.z - __bfloat162float(h2), s.w - __bfloat162float(h3));
    *(uint2*)(rb + t * 8) = hv;
    *(uint2*)(rb + 512 + t * 8) = lv;

    float ss = s.x * s.x + s.y * s.y + s.z * s.z + s.w * s.w;
    #pragma unroll
    for (int o = 16; o > 0; o >>= 1) ss += __shfl_xor_sync(0xffffffffu, ss, o);
    __shared__ float part[2];
    if ((t & 31) == 0) part[t >> 5] = ss;
    __syncthreads();
    if (t == 0) *sqdst = part[0] + part[1];
}

// ---------------------------------------------------------------------------
// Kernel 2: mma.sync bf16 mining GEMM, j-split 4 quarters, 512 threads.
// 16 warps in 4x4; warp tile 32x32. Quarter q: pos j-tiles [4q,4q+4),
// neg j-tiles [4q,4q+4); 8 local tiles x 4 chunks = 32 chunks.
// Same 3-segment hi/lo numerics and 3-stage ring as the passing R13 kernel.
// ---------------------------------------------------------------------------
#define OFF_A   0u
#define OFF_B   131072u
#define OFF_YY0 229376u
#define OFF_YY1 229888u
#define SMEM_SZ 230400
#define NCHUNK  32

__device__ __forceinline__ void prefetch_chunk(int g, int q, int tid, uint32_t sbase,
                                               const unsigned char* posb,
                                               const unsigned char* negb,
                                               const float* psq, const float* nsq) {
    int lt = g >> 2, c = g & 3;          // lt in 0..7
    int gjt = q * 4 + (lt & 3);          // global j-tile 0..15
    bool isp = lt < 4;
    const unsigned char* rb = (isp ? posb : negb) + (size_t)(gjt * 128) * ROW_BYTES;
    rb += c * 256;
    uint32_t dst = sbase + OFF_B + (uint32_t)(((uint32_t)g) % 3u) * 32768u;
    #pragma unroll
    for (int it = 0; it < 4; it++) {
        int i = tid + it * 512;
        int r = i >> 4, cl = i & 15;
        uint32_t cls16 = (uint32_t)((cl & 8) | ((cl ^ r) & 7));
        CP_ASYNC16(dst + (uint32_t)r * 256u + cls16 * 16u,
                   rb + (size_t)r * ROW_BYTES + cl * 16);
    }
    if (c == 0 && tid < 32) {
        const float* ys = (isp ? psq : nsq) + gjt * 128;
        CP_ASYNC16(sbase + ((lt & 1) ? OFF_YY1 : OFF_YY0) + (uint32_t)tid * 16u,
                   ys + tid * 4);
    }
}

__global__ void __launch_bounds__(512, 1) mine_kernel() {
    extern __shared__ __align__(16) unsigned char smem[];
    const int cls  = blockIdx.y;
    const int row0 = blockIdx.x * 128;
    const int q    = blockIdx.z;
    const int tid  = threadIdx.x;
    const int lane = tid & 31;
    const int wid  = tid >> 5;
    const int wm   = wid >> 2;        // 0..3 (32-row group)
    const int wn   = wid & 3;         // 0..3 (32-col group)
    const uint32_t sbase = smem_u32(smem);

    const unsigned char* posb = g_posb + (size_t)cls * PP * ROW_BYTES;
    const unsigned char* negb = g_negb + (size_t)cls * QQ * ROW_BYTES;
    const float* psq = g_pos_sq + cls * PP;
    const float* nsq = g_neg_sq + cls * QQ;

    // ---- resident A ext tile (128 rows x 1KB), XOR-swizzled ----
    {
        const unsigned char* asrc = posb + (size_t)row0 * ROW_BYTES;
        #pragma unroll
        for (int it = 0; it < 16; it++) {
            int i = tid + it * 512;          // 0..8191
            int r = i >> 6, c16 = i & 63;
            uint32_t c16s = (uint32_t)((c16 & ~7) | ((c16 ^ r) & 7));
            CP_ASYNC16(sbase + OFF_A + (uint32_t)r * 1024u + c16s * 16u,
                       asrc + (size_t)r * ROW_BYTES + c16 * 16);
        }
    }
    CP_COMMIT();
    prefetch_chunk(0, q, tid, sbase, posb, negb, psq, nsq);
    CP_COMMIT();
    prefetch_chunk(1, q, tid, sbase, posb, negb, psq, nsq);
    CP_COMMIT();

    // ---- per-lane constants ----
    const int rrA = wm * 32 + (lane & 15);          // A ldmatrix row
    const int khA = (lane >> 4) & 1;
    const int rB  = wn * 32 + (lane & 7) + (((lane >> 4) & 1) << 3);  // B x4 row
    const int rB7 = rB & 7;
    const int khB = (lane >> 3) & 1;
    uint32_t aRow[2];
    #pragma unroll
    for (int mt = 0; mt < 2; mt++)
        aRow[mt] = sbase + OFF_A + (uint32_t)(rrA + mt * 16) * 1024u;

    float xxv[4];
    #pragma unroll
    for (int mt = 0; mt < 2; mt++) {
        int r0 = wm * 32 + mt * 16 + (lane >> 2);
        xxv[mt * 2]     = psq[row0 + r0];
        xxv[mt * 2 + 1] = psq[row0 + r0 + 8];
    }

    float acc[32];
    #pragma unroll
    for (int i = 0; i < 32; i++) acc[i] = 0.0f;

    float bpv[4], bnv[4];
    int   bpj[4], bnj[4];
    #pragma unroll
    for (int i = 0; i < 4; i++) {
        bpv[i] = -1e30f; bpj[i] = 0;
        bnv[i] =  1e30f; bnj[i] = 0;
    }

    for (int g = 0; g < NCHUNK; g++) {
        CP_WAIT1();
        __syncthreads();
        if (g + 2 < NCHUNK)
            prefetch_chunk(g + 2, q, tid, sbase, posb, negb, psq, nsq);
        CP_COMMIT();

        const int lt = g >> 2, c = g & 3;
        const uint32_t sbB = sbase + OFF_B + (uint32_t)(((uint32_t)g) % 3u) * 32768u;
        uint32_t bRow[2];
        #pragma unroll
        for (int n2 = 0; n2 < 2; n2++)
            bRow[n2] = sbB + (uint32_t)(rB + n2 * 16) * 256u;

        const int uhi = (c & 1) * 16;
        #pragma unroll
        for (int s = 0; s < 8; s++) {
            // B: one x4 per 16-col pair -> {tile0 b0,b1, tile1 b0,b1}
            uint32_t b[2][4];
            #pragma unroll
            for (int n2 = 0; n2 < 2; n2++) {
                int cl = s * 2 + khB;
                uint32_t cls16 = (uint32_t)((cl & 8) | ((cl ^ rB7) & 7));
                LDSM_X4(b[n2][0], b[n2][1], b[n2][2], b[n2][3], bRow[n2] + cls16 * 16u);
            }
            // A hi segment
            {
                uint32_t a0[2], a1[2], a2[2], a3[2];
                #pragma unroll
                for (int mt = 0; mt < 2; mt++) {
                    int u = uhi + s * 2 + khA;
                    uint32_t us = (uint32_t)((u & ~7) | ((u ^ rrA) & 7));
                    LDSM_X4(a0[mt], a1[mt], a2[mt], a3[mt], aRow[mt] + us * 16u);
                }
                #pragma unroll
                for (int mt = 0; mt < 2; mt++)
                    #pragma unroll
                    for (int n2 = 0; n2 < 2; n2++) {
                        int ai0 = (mt * 4 + n2 * 2) * 4;
                        MMA16816(acc[ai0], acc[ai0 + 1], acc[ai0 + 2], acc[ai0 + 3],
                                 a0[mt], a1[mt], a2[mt], a3[mt], b[n2][0], b[n2][1]);
                        int ai1 = (mt * 4 + n2 * 2 + 1) * 4;
                        MMA16816(acc[ai1], acc[ai1 + 1], acc[ai1 + 2], acc[ai1 + 3],
                                 a0[mt], a1[mt], a2[mt], a3[mt], b[n2][2], b[n2][3]);
                    }
            }
            // A lo segment (only while B chunk is a hi chunk)
            if (c < 2) {
                const int ulo = 32 + (c & 1) * 16;
                uint32_t a0[2], a1[2], a2[2], a3[2];
                #pragma unroll
                for (int mt = 0; mt < 2; mt++) {
                    int u = ulo + s * 2 + khA;
                    uint32_t us = (uint32_t)((u & ~7) | ((u ^ rrA) & 7));
                    LDSM_X4(a0[mt], a1[mt], a2[mt], a3[mt], aRow[mt] + us * 16u);
                }
                #pragma unroll
                for (int mt = 0; mt < 2; mt++)
                    #pragma unroll
                    for (int n2 = 0; n2 < 2; n2++) {
                        int ai0 = (mt * 4 + n2 * 2) * 4;
                        MMA16816(acc[ai0], acc[ai0 + 1], acc[ai0 + 2], acc[ai0 + 3],
                                 a0[mt], a1[mt], a2[mt], a3[mt], b[n2][0], b[n2][1]);
                        int ai1 = (mt * 4 + n2 * 2 + 1) * 4;
                        MMA16816(acc[ai1], acc[ai1 + 1], acc[ai1 + 2], acc[ai1 + 3],
                                 a0[mt], a1[mt], a2[mt], a3[mt], b[n2][2], b[n2][3]);
                    }
            }
        }

        if (c == 3) {
            const float* yy = (const float*)(smem + ((lt & 1) ? OFF_YY1 : OFF_YY0));
            const bool isneg = lt >= 4;
            const int gjt = q * 4 + (lt & 3);
            const int jbase = gjt * 128 + wn * 32;
            #pragma unroll
            for (int mt = 0; mt < 2; mt++) {
                #pragma unroll
                for (int nt = 0; nt < 4; nt++) {
                    int ai = (mt * 4 + nt) * 4;
                    int n = nt * 8 + ((lane & 3) << 1);
                    float y0 = yy[wn * 32 + n], y1 = yy[wn * 32 + n + 1];
                    float d00 = fmaxf(fmaf(-2.0f, acc[ai],     xxv[mt*2]   + y0), 0.0f);
                    float d01 = fmaxf(fmaf(-2.0f, acc[ai + 1], xxv[mt*2]   + y1), 0.0f);
                    float d10 = fmaxf(fmaf(-2.0f, acc[ai + 2], xxv[mt*2+1] + y0), 0.0f);
                    float d11 = fmaxf(fmaf(-2.0f, acc[ai + 3], xxv[mt*2+1] + y1), 0.0f);
                    int j0 = jbase + n, j1 = j0 + 1;
                    if (!isneg) {
                        if (d00 > bpv[mt*2])   { bpv[mt*2]   = d00; bpj[mt*2]   = j0; }
                        if (d01 > bpv[mt*2])   { bpv[mt*2]   = d01; bpj[mt*2]   = j1; }
                        if (d10 > bpv[mt*2+1]) { bpv[mt*2+1] = d10; bpj[mt*2+1] = j0; }
                        if (d11 > bpv[mt*2+1]) { bpv[mt*2+1] = d11; bpj[mt*2+1] = j1; }
                    } else {
                        if (d00 < bnv[mt*2])   { bnv[mt*2]   = d00; bnj[mt*2]   = j0; }
                        if (d01 < bnv[mt*2])   { bnv[mt*2]   = d01; bnj[mt*2]   = j1; }
                        if (d10 < bnv[mt*2+1]) { bnv[mt*2+1] = d10; bnj[mt*2+1] = j0; }
                        if (d11 < bnv[mt*2+1]) { bnv[mt*2+1] = d11; bnj[mt*2+1] = j1; }
                    }
                    acc[ai] = acc[ai + 1] = acc[ai + 2] = acc[ai + 3] = 0.0f;
                }
            }
        }
    }

    // ---- cross-copy reduction (16 copies per row), index tie-break ----
    __syncthreads();
    float* sPV = (float*)(smem + OFF_B);
    int*   sPJ = (int*)(smem + OFF_B + 8192);
    float* sNV = (float*)(smem + OFF_B + 16384);
    int*   sNJ = (int*)(smem + OFF_B + 24576);
    int copy = wn * 4 + (lane & 3);
    #pragma unroll
    for (int mt = 0; mt < 2; mt++) {
        #pragma unroll
        for (int h = 0; h < 2; h++) {
            int r = wm * 32 + mt * 16 + (lane >> 2) + 8 * h;
            sPV[r * 16 + copy] = bpv[mt * 2 + h];
            sPJ[r * 16 + copy] = bpj[mt * 2 + h];
            sNV[r * 16 + copy] = bnv[mt * 2 + h];
            sNJ[r * 16 + copy] = bnj[mt * 2 + h];
        }
    }
    __syncthreads();
    if (tid < 128) {
        int r = tid;
        int outi = q * NP + cls * PP + row0 + r;
        float bv = sPV[r * 16]; int bj = sPJ[r * 16];
        #pragma unroll
        for (int x = 1; x < 16; x++) {
            float v = sPV[r * 16 + x]; int j = sPJ[r * 16 + x];
            if (v > bv || (v == bv && j < bj)) { bv = v; bj = j; }
        }
        g_qpv[outi] = bv; g_qpj[outi] = bj;
        bv = sNV[r * 16]; bj = sNJ[r * 16];
        #pragma unroll
        for (int x = 1; x < 16; x++) {
            float v = sNV[r * 16 + x]; int j = sNJ[r * 16 + x];
            if (v < bv || (v == bv && j < bj)) { bv = v; bj = j; }
        }
        g_qnv[outi] = bv; g_qnj[outi] = bj;
    }
}

// ---------------------------------------------------------------------------
// Kernel 2b: merge 4 quarters per anchor (ascending q = ascending j ranges).
// ---------------------------------------------------------------------------
__global__ void __launch_bounds__(256) merge_kernel() {
    int a = blockIdx.x * 256 + threadIdx.x;
    if (a >= NP) return;
    float bv = g_qpv[a]; int bj = g_qpj[a];
    #pragma unroll
    for (int qq = 1; qq < 4; qq++) {
        float v = g_qpv[qq * NP + a]; int j = g_qpj[qq * NP + a];
        if (v > bv || (v == bv && j < bj)) { bv = v; bj = j; }
    }
    g_hp[a] = bj;
    bv = g_qnv[a]; bj = g_qnj[a];
    #pragma unroll
    for (int qq = 1; qq < 4; qq++) {
        float v = g_qnv[qq * NP + a]; int j = g_qnj[qq * NP + a];
        if (v < bv || (v == bv && j < bj)) { bv = v; bj = j; }
    }
    g_hn[a] = bj;
}

// ---------------------------------------------------------------------------
// Kernel 3: per-anchor pdist + hinge from reconstructed x = hi + lo
// (error ~2^-17 relative). One warp per anchor, lane = one 8-elem chunk.
// ---------------------------------------------------------------------------
__global__ void __launch_bounds__(256) loss_kernel() {
    int warp = threadIdx.x >> 5;
    int lane = threadIdx.x & 31;
    int a = blockIdx.x * 8 + warp;
    int cls = a / PP;

    const unsigned char* xb = g_posb + (size_t)a * ROW_BYTES;
    const unsigned char* pb = g_posb + (size_t)(cls * PP + g_hp[a]) * ROW_BYTES;
    const unsigned char* nb = g_negb + (size_t)(cls * QQ + g_hn[a]) * ROW_BYTES;

    uint4 xh = *(const uint4*)(xb + lane * 16);
    uint4 xl = *(const uint4*)(xb + 512 + lane * 16);
    uint4 ph = *(const uint4*)(pb + lane * 16);
    uint4 pl = *(const uint4*)(pb + 512 + lane * 16);
    uint4 nh = *(const uint4*)(nb + lane * 16);
    uint4 nl = *(const uint4*)(nb + 512 + lane * 16);

    const uint32_t* xhw = (const uint32_t*)&xh;
    const uint32_t* xlw = (const uint32_t*)&xl;
    const uint32_t* phw = (const uint32_t*)&ph;
    const uint32_t* plw = (const uint32_t*)&pl;
    const uint32_t* nhw = (const uint32_t*)&nh;
    const uint32_t* nlw = (const uint32_t*)&nl;

    float sp = 0.0f, sn = 0.0f;
    #pragma unroll
    for (int w = 0; w < 4; w++) {
        float2 xhf = bf2f(xhw[w]), xlf = bf2f(xlw[w]);
        float2 phf = bf2f(phw[w]), plf = bf2f(plw[w]);
        float2 nhf = bf2f(nhw[w]), nlf = bf2f(nlw[w]);
        float x0 = xhf.x + xlf.x, x1 = xhf.y + xlf.y;
        float p0 = phf.x + plf.x, p1 = phf.y + plf.y;
        float n0 = nhf.x + nlf.x, n1 = nhf.y + nlf.y;
        float d;
        d = x0 - p0; sp = fmaf(d, d, sp);
        d = x1 - p1; sp = fmaf(d, d, sp);
        d = x0 - n0; sn = fmaf(d, d, sn);
        d = x1 - n1; sn = fmaf(d, d, sn);
    }
    #pragma unroll
    for (int o = 16; o > 0; o >>= 1) {
        sp += __shfl_xor_sync(0xffffffffu, sp, o);
        sn += __shfl_xor_sync(0xffffffffu, sn, o);
    }
    __shared__ float sl[8];
    if (lane == 0) {
        float dp = sqrtf(fmaxf(sp, 0.0f) + EPSV);
        float dn = sqrtf(fmaxf(sn, 0.0f) + EPSV);
        sl[warp] = fmaxf(0.3f + dp - dn, 0.0f);
    }
    __syncthreads();
    if (threadIdx.x == 0) {
        float s = 0.0f;
        #pragma unroll
        for (int w = 0; w < 8; w++) s += sl[w];
        g_partial[blockIdx.x] = s * (1.0f / (float)PP);
    }
}

__global__ void __launch_bounds__(1024) finalsum_kernel(float* __restrict__ out) {
    __shared__ float s[1024];
    float v = 0.0f;
    for (int i = threadIdx.x; i < NP / 8; i += 1024) v += g_partial[i];
    s[threadIdx.x] = v;
    __syncthreads();
    for (int st = 512; st > 0; st >>= 1) {
        if (threadIdx.x < st) s[threadIdx.x] += s[threadIdx.x + st];
        __syncthreads();
    }
    if (threadIdx.x == 0) out[0] = s[0];
}

extern "C" void kernel_launch(void* const* d_in, const int* in_sizes, int n_in,
                              void* d_out, int out_size) {
    const float* feat = (const float*)d_in[0];
    const int* pidx = (const int*)d_in[1];
    const int* nidx = (const int*)d_in[2];
    float* out = (float*)d_out;

    cudaFuncSetAttribute(mine_kernel, cudaFuncAttributeMaxDynamicSharedMemorySize, SMEM_SZ);

    gather_kernel<<<NCLS * (PP + QQ), 64>>>(feat, pidx, nidx);
    mine_kernel<<<dim3(PP / 128, NCLS, 4), 512, SMEM_SZ>>>();
    merge_kernel<<<(NP + 255) / 256, 256>>>();
    loss_kernel<<<NP / 8, 256>>>();
    finalsum_kernel<<<1, 1024>>>(out);
}

// round 17
// speedup vs baseline: 1.0416x; 1.0416x over previous
#include <cuda_runtime.h>
#include <cuda_bf16.h>
#include <math.h>
#include <stdint.h>

// ---------------- problem constants ----------------
#define NCLS 20
#define PP 2048
#define QQ 2048
#define CC 256
#define EPSV (0.0001f / 256.0f)
#define NP (NCLS * PP)

// ext row: [hi(256) | lo(256)] bf16 = 1024 bytes
#define ROW_BYTES 1024

// ---------------- device scratch (static; no runtime alloc) ----------------
__device__ float g_pos_sq[NCLS * PP];
__device__ float g_neg_sq[NCLS * QQ];
__device__ __align__(16) unsigned char g_posb[(size_t)NCLS * PP * ROW_BYTES];
__device__ __align__(16) unsigned char g_negb[(size_t)NCLS * QQ * ROW_BYTES];
__device__ float g_qpv[4 * NP];
__device__ int   g_qpj[4 * NP];
__device__ float g_qnv[4 * NP];
__device__ int   g_qnj[4 * NP];
__device__ int   g_hp[NP];
__device__ int   g_hn[NP];
__device__ float g_partial[NP / 8];

// ---------------- helpers ----------------
__device__ __forceinline__ uint32_t smem_u32(const void* p) {
    uint32_t a;
    asm("{ .reg .u64 t; cvta.to.shared.u64 t, %1; cvt.u32.u64 %0, t; }" : "=r"(a) : "l"(p));
    return a;
}
#define CP_ASYNC16(saddr, gptr) \
    asm volatile("cp.async.cg.shared.global [%0], [%1], 16;" :: "r"(saddr), "l"(gptr))
#define CP_COMMIT() asm volatile("cp.async.commit_group;" ::: "memory")
#define CP_WAIT1()  asm volatile("cp.async.wait_group 1;" ::: "memory")

#define LDSM_X4(r0, r1, r2, r3, a) \
    asm volatile("ldmatrix.sync.aligned.m8n8.x4.shared.b16 {%0,%1,%2,%3}, [%4];" \
                 : "=r"(r0), "=r"(r1), "=r"(r2), "=r"(r3) : "r"(a))
#define LDSM_X2(r0, r1, a) \
    asm volatile("ldmatrix.sync.aligned.m8n8.x2.shared.b16 {%0,%1}, [%2];" \
                 : "=r"(r0), "=r"(r1) : "r"(a))
#define MMA16816(c0, c1, c2, c3, a0, a1, a2, a3, b0, b1) \
    asm volatile("mma.sync.aligned.m16n8k16.row.col.f32.bf16.bf16.f32 " \
                 "{%0,%1,%2,%3}, {%4,%5,%6,%7}, {%8,%9}, {%0,%1,%2,%3};" \
                 : "+f"(c0), "+f"(c1), "+f"(c2), "+f"(c3) \
                 : "r"(a0), "r"(a1), "r"(a2), "r"(a3), "r"(b0), "r"(b1))

__device__ __forceinline__ uint32_t pack_bf16(float a, float b) {
    __nv_bfloat16 ba = __float2bfloat16(a);
    __nv_bfloat16 bb = __float2bfloat16(b);
    uint16_t ua = *reinterpret_cast<uint16_t*>(&ba);
    uint16_t ub = *reinterpret_cast<uint16_t*>(&bb);
    return ((uint32_t)ub << 16) | (uint32_t)ua;
}
__device__ __forceinline__ float2 bf2f(uint32_t u) {
    __nv_bfloat162 b = *reinterpret_cast<__nv_bfloat162*>(&u);
    float2 r;
    r.x = __bfloat162float(b.x);
    r.y = __bfloat162float(b.y);
    return r;
}

// ---------------------------------------------------------------------------
// Kernel 1: gather + sigmoid -> hi|lo bf16 ext row + squared norm.
// (no fp32 rows; loss reconstructs x = hi + lo, error ~2^-17.)
// ---------------------------------------------------------------------------
__global__ void __launch_bounds__(64) gather_kernel(const float* __restrict__ feat,
                                                    const int* __restrict__ pidx,
                                                    const int* __restrict__ nidx) {
    int row = blockIdx.x;
    int t = threadIdx.x;
    int src;
    float* sqdst;
    unsigned char* rb;
    if (row < NP) {
        src = pidx[row];
        sqdst = g_pos_sq + row;
        rb = g_posb + (size_t)row * ROW_BYTES;
    } else {
        int r = row - NP;
        src = nidx[r];
        sqdst = g_neg_sq + r;
        rb = g_negb + (size_t)r * ROW_BYTES;
    }
    float4 v = *(const float4*)(feat + (size_t)src * CC + t * 4);
    float4 s;
    s.x = 1.0f / (1.0f + expf(-v.x));
    s.y = 1.0f / (1.0f + expf(-v.y));
    s.z = 1.0f / (1.0f + expf(-v.z));
    s.w = 1.0f / (1.0f + expf(-v.w));

    __nv_bfloat16 h0 = __float2bfloat16(s.x);
    __nv_bfloat16 h1 = __float2bfloat16(s.y);
    __nv_bfloat16 h2 = __float2bfloat16(s.z);
    __nv_bfloat16 h3 = __float2bfloat16(s.w);
    uint16_t u0 = *reinterpret_cast<uint16_t*>(&h0);
    uint16_t u1 = *reinterpret_cast<uint16_t*>(&h1);
    uint16_t u2 = *reinterpret_cast<uint16_t*>(&h2);
    uint16_t u3 = *reinterpret_cast<uint16_t*>(&h3);
    uint2 hv, lv;
    hv.x = ((uint32_t)u1 << 16) | u0;
    hv.y = ((uint32_t)u3 << 16) | u2;
    lv.x = pack_bf16(s.x - __bfloat162float(h0), s.y - __bfloat162float(h1));
    lv.y = pack_bf16(s.z - __bfloat162float(h2), s.w - __bfloat162float(h3));
    *(uint2*)(rb + t * 8) = hv;
    *(uint2*)(rb + 512 + t * 8) = lv;

    float ss = s.x * s.x + s.y * s.y + s.z * s.z + s.w * s.w;
    #pragma unroll
    for (int o = 16; o > 0; o >>= 1) ss += __shfl_xor_sync(0xffffffffu, ss, o);
    __shared__ float part[2];
    if ((t & 31) == 0) part[t >> 5] = ss;
    __syncthreads();
    if (t == 0) *sqdst = part[0] + part[1];
}

// ---------------------------------------------------------------------------
// Kernel 2: mma.sync bf16 mining GEMM (R15-proven 256-thread core).
// CTA = (128 anchors, class, quarter q), 8 warps in 2x4, warp tile 64x32.
// Quarter q: pos j-tiles [4q,4q+4), neg j-tiles [4q,4q+4); 32 chunks.
// 3-segment hi/lo numerics, 3-stage ring, one __syncthreads per chunk.
// ---------------------------------------------------------------------------
#define OFF_A   0u
#define OFF_B   131072u
#define OFF_YY0 229376u
#define OFF_YY1 229888u
#define SMEM_SZ 230400
#define NCHUNK  32

__device__ __forceinline__ void prefetch_chunk(int g, int q, int tid, uint32_t sbase,
                                               const unsigned char* posb,
                                               const unsigned char* negb,
                                               const float* psq, const float* nsq) {
    int lt = g >> 2, c = g & 3;          // lt in 0..7
    int gjt = q * 4 + (lt & 3);          // global j-tile 0..15
    bool isp = lt < 4;
    const unsigned char* rb = (isp ? posb : negb) + (size_t)(gjt * 128) * ROW_BYTES;
    rb += c * 256;
    uint32_t dst = sbase + OFF_B + (uint32_t)(((uint32_t)g) % 3u) * 32768u;
    #pragma unroll
    for (int it = 0; it < 8; it++) {
        int i = tid + it * 256;
        int r = i >> 4, cl = i & 15;
        uint32_t cls16 = (uint32_t)((cl & 8) | ((cl ^ r) & 7));
        CP_ASYNC16(dst + (uint32_t)r * 256u + cls16 * 16u,
                   rb + (size_t)r * ROW_BYTES + cl * 16);
    }
    if (c == 0 && tid < 32) {
        const float* ys = (isp ? psq : nsq) + gjt * 128;
        CP_ASYNC16(sbase + ((lt & 1) ? OFF_YY1 : OFF_YY0) + (uint32_t)tid * 16u,
                   ys + tid * 4);
    }
}

__global__ void __launch_bounds__(256, 1) mine_kernel() {
    extern __shared__ __align__(16) unsigned char smem[];
    const int cls  = blockIdx.y;
    const int row0 = blockIdx.x * 128;
    const int q    = blockIdx.z;
    const int tid  = threadIdx.x;
    const int lane = tid & 31;
    const int wid  = tid >> 5;
    const int wm   = wid >> 2;        // 0..1
    const int wn   = wid & 3;         // 0..3
    const uint32_t sbase = smem_u32(smem);

    const unsigned char* posb = g_posb + (size_t)cls * PP * ROW_BYTES;
    const unsigned char* negb = g_negb + (size_t)cls * QQ * ROW_BYTES;
    const float* psq = g_pos_sq + cls * PP;
    const float* nsq = g_neg_sq + cls * QQ;

    // ---- resident A ext tile (128 rows x 1KB), XOR-swizzled ----
    {
        const unsigned char* asrc = posb + (size_t)row0 * ROW_BYTES;
        #pragma unroll
        for (int it = 0; it < 32; it++) {
            int i = tid + it * 256;          // 0..8191
            int r = i >> 6, c16 = i & 63;
            uint32_t c16s = (uint32_t)((c16 & ~7) | ((c16 ^ r) & 7));
            CP_ASYNC16(sbase + OFF_A + (uint32_t)r * 1024u + c16s * 16u,
                       asrc + (size_t)r * ROW_BYTES + c16 * 16);
        }
    }
    CP_COMMIT();
    prefetch_chunk(0, q, tid, sbase, posb, negb, psq, nsq);
    CP_COMMIT();
    prefetch_chunk(1, q, tid, sbase, posb, negb, psq, nsq);
    CP_COMMIT();

    // ---- per-lane constants ----
    const int rrA = wm * 64 + (lane & 15);
    const int khA = (lane >> 4) & 1;
    const int nB  = wn * 32 + (lane & 7);
    const int khB = (lane >> 3) & 1;
    uint32_t aRow[4];
    #pragma unroll
    for (int mt = 0; mt < 4; mt++)
        aRow[mt] = sbase + OFF_A + (uint32_t)(rrA + mt * 16) * 1024u;

    float xxv[8];
    #pragma unroll
    for (int mt = 0; mt < 4; mt++) {
        int r0 = wm * 64 + mt * 16 + (lane >> 2);
        xxv[mt * 2]     = psq[row0 + r0];
        xxv[mt * 2 + 1] = psq[row0 + r0 + 8];
    }

    float acc[64];
    #pragma unroll
    for (int i = 0; i < 64; i++) acc[i] = 0.0f;

    float bpv[8], bnv[8];
    int   bpj[8], bnj[8];
    #pragma unroll
    for (int i = 0; i < 8; i++) {
        bpv[i] = -1e30f; bpj[i] = 0;
        bnv[i] =  1e30f; bnj[i] = 0;
    }

    for (int g = 0; g < NCHUNK; g++) {
        CP_WAIT1();
        __syncthreads();
        if (g + 2 < NCHUNK)
            prefetch_chunk(g + 2, q, tid, sbase, posb, negb, psq, nsq);
        CP_COMMIT();

        const int lt = g >> 2, c = g & 3;
        const uint32_t sbB = sbase + OFF_B + (uint32_t)(((uint32_t)g) % 3u) * 32768u;
        uint32_t bRow[4];
        #pragma unroll
        for (int nt = 0; nt < 4; nt++)
            bRow[nt] = sbB + (uint32_t)(nB + nt * 8) * 256u;

        const int uhi = (c & 1) * 16;
        if (c < 2) {
            const int ulo = 32 + (c & 1) * 16;
            #pragma unroll
            for (int s = 0; s < 8; s++) {
                uint32_t b0[4], b1[4];
                #pragma unroll
                for (int nt = 0; nt < 4; nt++) {
                    int cl = s * 2 + khB;
                    uint32_t cls16 = (uint32_t)((cl & 8) | ((cl ^ nB) & 7));
                    LDSM_X2(b0[nt], b1[nt], bRow[nt] + cls16 * 16u);
                }
                {
                    uint32_t a0[4], a1[4], a2[4], a3[4];
                    #pragma unroll
                    for (int mt = 0; mt < 4; mt++) {
                        int u = uhi + s * 2 + khA;
                        uint32_t us = (uint32_t)((u & ~7) | ((u ^ rrA) & 7));
                        LDSM_X4(a0[mt], a1[mt], a2[mt], a3[mt], aRow[mt] + us * 16u);
                    }
                    #pragma unroll
                    for (int mt = 0; mt < 4; mt++)
                        #pragma unroll
                        for (int nt = 0; nt < 4; nt++) {
                            int ai = (mt * 4 + nt) * 4;
                            MMA16816(acc[ai], acc[ai + 1], acc[ai + 2], acc[ai + 3],
                                     a0[mt], a1[mt], a2[mt], a3[mt], b0[nt], b1[nt]);
                        }
                }
                {
                    uint32_t a0[4], a1[4], a2[4], a3[4];
                    #pragma unroll
                    for (int mt = 0; mt < 4; mt++) {
                        int u = ulo + s * 2 + khA;
                        uint32_t us = (uint32_t)((u & ~7) | ((u ^ rrA) & 7));
                        LDSM_X4(a0[mt], a1[mt], a2[mt], a3[mt], aRow[mt] + us * 16u);
                    }
                    #pragma unroll
                    for (int mt = 0; mt < 4; mt++)
                        #pragma unroll
                        for (int nt = 0; nt < 4; nt++) {
                            int ai = (mt * 4 + nt) * 4;
                            MMA16816(acc[ai], acc[ai + 1], acc[ai + 2], acc[ai + 3],
                                     a0[mt], a1[mt], a2[mt], a3[mt], b0[nt], b1[nt]);
                        }
                }
            }
        } else {
            #pragma unroll
            for (int s = 0; s < 8; s++) {
                uint32_t b0[4], b1[4];
                #pragma unroll
                for (int nt = 0; nt < 4; nt++) {
                    int cl = s * 2 + khB;
                    uint32_t cls16 = (uint32_t)((cl & 8) | ((cl ^ nB) & 7));
                    LDSM_X2(b0[nt], b1[nt], bRow[nt] + cls16 * 16u);
                }
                uint32_t a0[4], a1[4], a2[4], a3[4];
                #pragma unroll
                for (int mt = 0; mt < 4; mt++) {
                    int u = uhi + s * 2 + khA;
                    uint32_t us = (uint32_t)((u & ~7) | ((u ^ rrA) & 7));
                    LDSM_X4(a0[mt], a1[mt], a2[mt], a3[mt], aRow[mt] + us * 16u);
                }
                #pragma unroll
                for (int mt = 0; mt < 4; mt++)
                    #pragma unroll
                    for (int nt = 0; nt < 4; nt++) {
                        int ai = (mt * 4 + nt) * 4;
                        MMA16816(acc[ai], acc[ai + 1], acc[ai + 2], acc[ai + 3],
                                 a0[mt], a1[mt], a2[mt], a3[mt], b0[nt], b1[nt]);
                    }
            }
        }

        if (c == 3) {
            const float* yy = (const float*)(smem + ((lt & 1) ? OFF_YY1 : OFF_YY0));
            const bool isneg = lt >= 4;
            const int gjt = q * 4 + (lt & 3);
            const int jbase = gjt * 128 + wn * 32;
            #pragma unroll
            for (int mt = 0; mt < 4; mt++) {
                #pragma unroll
                for (int nt = 0; nt < 4; nt++) {
                    int ai = (mt * 4 + nt) * 4;
                    int n = nt * 8 + ((lane & 3) << 1);
                    float y0 = yy[wn * 32 + n], y1 = yy[wn * 32 + n + 1];
                    float d00 = fmaxf(fmaf(-2.0f, acc[ai],     xxv[mt*2]   + y0), 0.0f);
                    float d01 = fmaxf(fmaf(-2.0f, acc[ai + 1], xxv[mt*2]   + y1), 0.0f);
                    float d10 = fmaxf(fmaf(-2.0f, acc[ai + 2], xxv[mt*2+1] + y0), 0.0f);
                    float d11 = fmaxf(fmaf(-2.0f, acc[ai + 3], xxv[mt*2+1] + y1), 0.0f);
                    int j0 = jbase + n, j1 = j0 + 1;
                    if (!isneg) {
                        if (d00 > bpv[mt*2])   { bpv[mt*2]   = d00; bpj[mt*2]   = j0; }
                        if (d01 > bpv[mt*2])   { bpv[mt*2]   = d01; bpj[mt*2]   = j1; }
                        if (d10 > bpv[mt*2+1]) { bpv[mt*2+1] = d10; bpj[mt*2+1] = j0; }
                        if (d11 > bpv[mt*2+1]) { bpv[mt*2+1] = d11; bpj[mt*2+1] = j1; }
                    } else {
                        if (d00 < bnv[mt*2])   { bnv[mt*2]   = d00; bnj[mt*2]   = j0; }
                        if (d01 < bnv[mt*2])   { bnv[mt*2]   = d01; bnj[mt*2]   = j1; }
                        if (d10 < bnv[mt*2+1]) { bnv[mt*2+1] = d10; bnj[mt*2+1] = j0; }
                        if (d11 < bnv[mt*2+1]) { bnv[mt*2+1] = d11; bnj[mt*2+1] = j1; }
                    }
                    acc[ai] = acc[ai + 1] = acc[ai + 2] = acc[ai + 3] = 0.0f;
                }
            }
        }
    }

    // ---- cross-copy reduction (16 copies per row), index tie-break ----
    __syncthreads();
    float* sPV = (float*)(smem + OFF_B);
    int*   sPJ = (int*)(smem + OFF_B + 8192);
    float* sNV = (float*)(smem + OFF_B + 16384);
    int*   sNJ = (int*)(smem + OFF_B + 24576);
    int copy = wn * 4 + (lane & 3);
    #pragma unroll
    for (int mt = 0; mt < 4; mt++) {
        #pragma unroll
        for (int h = 0; h < 2; h++) {
            int r = wm * 64 + mt * 16 + (lane >> 2) + 8 * h;
            sPV[r * 16 + copy] = bpv[mt * 2 + h];
            sPJ[r * 16 + copy] = bpj[mt * 2 + h];
            sNV[r * 16 + copy] = bnv[mt * 2 + h];
            sNJ[r * 16 + copy] = bnj[mt * 2 + h];
        }
    }
    __syncthreads();
    if (tid < 128) {
        int r = tid;
        int outi = q * NP + cls * PP + row0 + r;
        float bv = sPV[r * 16]; int bj = sPJ[r * 16];
        #pragma unroll
        for (int x = 1; x < 16; x++) {
            float v = sPV[r * 16 + x]; int j = sPJ[r * 16 + x];
            if (v > bv || (v == bv && j < bj)) { bv = v; bj = j; }
        }
        g_qpv[outi] = bv; g_qpj[outi] = bj;
        bv = sNV[r * 16]; bj = sNJ[r * 16];
        #pragma unroll
        for (int x = 1; x < 16; x++) {
            float v = sNV[r * 16 + x]; int j = sNJ[r * 16 + x];
            if (v < bv || (v == bv && j < bj)) { bv = v; bj = j; }
        }
        g_qnv[outi] = bv; g_qnj[outi] = bj;
    }
}

// ---------------------------------------------------------------------------
// Kernel 2b: merge 4 quarters per anchor (ascending q = ascending j ranges).
// ---------------------------------------------------------------------------
__global__ void __launch_bounds__(256) merge_kernel() {
    int a = blockIdx.x * 256 + threadIdx.x;
    if (a >= NP) return;
    float bv = g_qpv[a]; int bj = g_qpj[a];
    #pragma unroll
    for (int qq = 1; qq < 4; qq++) {
        float v = g_qpv[qq * NP + a]; int j = g_qpj[qq * NP + a];
        if (v > bv || (v == bv && j < bj)) { bv = v; bj = j; }
    }
    g_hp[a] = bj;
    bv = g_qnv[a]; bj = g_qnj[a];
    #pragma unroll
    for (int qq = 1; qq < 4; qq++) {
        float v = g_qnv[qq * NP + a]; int j = g_qnj[qq * NP + a];
        if (v < bv || (v == bv && j < bj)) { bv = v; bj = j; }
    }
    g_hn[a] = bj;
}

// ---------------------------------------------------------------------------
// Kernel 3: per-anchor pdist + hinge from reconstructed x = hi + lo
// (error ~2^-17 relative). One warp per anchor, lane = one 8-elem chunk.
// ---------------------------------------------------------------------------
__global__ void __launch_bounds__(256) loss_kernel() {
    int warp = threadIdx.x >> 5;
    int lane = threadIdx.x & 31;
    int a = blockIdx.x * 8 + warp;
    int cls = a / PP;

    const unsigned char* xb = g_posb + (size_t)a * ROW_BYTES;
    const unsigned char* pb = g_posb + (size_t)(cls * PP + g_hp[a]) * ROW_BYTES;
    const unsigned char* nb = g_negb + (size_t)(cls * QQ + g_hn[a]) * ROW_BYTES;

    uint4 xh = *(const uint4*)(xb + lane * 16);
    uint4 xl = *(const uint4*)(xb + 512 + lane * 16);
    uint4 ph = *(const uint4*)(pb + lane * 16);
    uint4 pl = *(const uint4*)(pb + 512 + lane * 16);
    uint4 nh = *(const uint4*)(nb + lane * 16);
    uint4 nl = *(const uint4*)(nb + 512 + lane * 16);

    const uint32_t* xhw = (const uint32_t*)&xh;
    const uint32_t* xlw = (const uint32_t*)&xl;
    const uint32_t* phw = (const uint32_t*)&ph;
    const uint32_t* plw = (const uint32_t*)&pl;
    const uint32_t* nhw = (const uint32_t*)&nh;
    const uint32_t* nlw = (const uint32_t*)&nl;

    float sp = 0.0f, sn = 0.0f;
    #pragma unroll
    for (int w = 0; w < 4; w++) {
        float2 xhf = bf2f(xhw[w]), xlf = bf2f(xlw[w]);
        float2 phf = bf2f(phw[w]), plf = bf2f(plw[w]);
        float2 nhf = bf2f(nhw[w]), nlf = bf2f(nlw[w]);
        float x0 = xhf.x + xlf.x, x1 = xhf.y + xlf.y;
        float p0 = phf.x + plf.x, p1 = phf.y + plf.y;
        float n0 = nhf.x + nlf.x, n1 = nhf.y + nlf.y;
        float d;
        d = x0 - p0; sp = fmaf(d, d, sp);
        d = x1 - p1; sp = fmaf(d, d, sp);
        d = x0 - n0; sn = fmaf(d, d, sn);
        d = x1 - n1; sn = fmaf(d, d, sn);
    }
    #pragma unroll
    for (int o = 16; o > 0; o >>= 1) {
        sp += __shfl_xor_sync(0xffffffffu, sp, o);
        sn += __shfl_xor_sync(0xffffffffu, sn, o);
    }
    __shared__ float sl[8];
    if (lane == 0) {
        float dp = sqrtf(fmaxf(sp, 0.0f) + EPSV);
        float dn = sqrtf(fmaxf(sn, 0.0f) + EPSV);
        sl[warp] = fmaxf(0.3f + dp - dn, 0.0f);
    }
    __syncthreads();
    if (threadIdx.x == 0) {
        float s = 0.0f;
        #pragma unroll
        for (int w = 0; w < 8; w++) s += sl[w];
        g_partial[blockIdx.x] = s * (1.0f / (float)PP);
    }
}

__global__ void __launch_bounds__(1024) finalsum_kernel(float* __restrict__ out) {
    __shared__ float s[1024];
    float v = 0.0f;
    for (int i = threadIdx.x; i < NP / 8; i += 1024) v += g_partial[i];
    s[threadIdx.x] = v;
    __syncthreads();
    for (int st = 512; st > 0; st >>= 1) {
        if (threadIdx.x < st) s[threadIdx.x] += s[threadIdx.x + st];
        __syncthreads();
    }
    if (threadIdx.x == 0) out[0] = s[0];
}

extern "C" void kernel_launch(void* const* d_in, const int* in_sizes, int n_in,
                              void* d_out, int out_size) {
    const float* feat = (const float*)d_in[0];
    const int* pidx = (const int*)d_in[1];
    const int* nidx = (const int*)d_in[2];
    float* out = (float*)d_out;

    cudaFuncSetAttribute(mine_kernel, cudaFuncAttributeMaxDynamicSharedMemorySize, SMEM_SZ);

    gather_kernel<<<NCLS * (PP + QQ), 64>>>(feat, pidx, nidx);
    mine_kernel<<<dim3(PP / 128, NCLS, 4), 256, SMEM_SZ>>>();
    merge_kernel<<<(NP + 255) / 256, 256>>>();
    loss_kernel<<<NP / 8, 256>>>();
    finalsum_kernel<<<1, 1024>>>(out);
}